// round 3
// baseline (speedup 1.0000x reference)
#include <cuda_runtime.h>

// FLoss: mean((1 - output[i, target[i]])^2)
// output: f32 [N,2]; target: int32 [N]  (jax x64-disabled downcasts int64->int32)
// HBM-bound streaming reduction: 192 MB in, 4 B out.

#define NBLOCKS 1024
#define NTHREADS 256

__device__ float g_partials[NBLOCKS];

__device__ __forceinline__ float quad_term(float4 v0, float4 v1, int4 t) {
    float a = (t.x == 0) ? v0.x : v0.y;
    float b = (t.y == 0) ? v0.z : v0.w;
    float c = (t.z == 0) ? v1.x : v1.y;
    float d = (t.w == 0) ? v1.z : v1.w;
    float da = 1.0f - a, db = 1.0f - b, dc = 1.0f - c, dd = 1.0f - d;
    float s0 = fmaf(da, da, db * db);
    float s1 = fmaf(dc, dc, dd * dd);
    return s0 + s1;
}

__global__ __launch_bounds__(NTHREADS)
void floss_partial_kernel(const float* __restrict__ out,
                          const int* __restrict__ tgt,
                          long long nq /* = N/4 */) {
    const float4* outv = reinterpret_cast<const float4*>(out);  // 2 rows per float4
    const int4*   tgtv = reinterpret_cast<const int4*>(tgt);    // 4 targets per int4

    float acc = 0.0f;
    long long j = (long long)blockIdx.x * NTHREADS + threadIdx.x;
    const long long stride = (long long)NBLOCKS * NTHREADS;

    // Unroll-by-2: 6 independent loads in flight per thread per trip.
    for (; j + stride < nq; j += 2 * stride) {
        float4 a0 = outv[2 * j];
        float4 a1 = outv[2 * j + 1];
        int4   ta = tgtv[j];
        long long k = j + stride;
        float4 b0 = outv[2 * k];
        float4 b1 = outv[2 * k + 1];
        int4   tb = tgtv[k];

        acc += quad_term(a0, a1, ta);
        acc += quad_term(b0, b1, tb);
    }
    // Remainder
    for (; j < nq; j += stride) {
        float4 a0 = outv[2 * j];
        float4 a1 = outv[2 * j + 1];
        int4   ta = tgtv[j];
        acc += quad_term(a0, a1, ta);
    }

    // Block reduction
    #pragma unroll
    for (int off = 16; off > 0; off >>= 1)
        acc += __shfl_xor_sync(0xFFFFFFFFu, acc, off);

    __shared__ float warp_sums[NTHREADS / 32];
    int lane = threadIdx.x & 31;
    int wid  = threadIdx.x >> 5;
    if (lane == 0) warp_sums[wid] = acc;
    __syncthreads();

    if (wid == 0) {
        float v = (lane < NTHREADS / 32) ? warp_sums[lane] : 0.0f;
        #pragma unroll
        for (int off = 4; off > 0; off >>= 1)
            v += __shfl_xor_sync(0xFFFFFFFFu, v, off);
        if (lane == 0) g_partials[blockIdx.x] = v;
    }
}

__global__ __launch_bounds__(NTHREADS)
void floss_final_kernel(float* __restrict__ d_out, float inv_n) {
    float acc = 0.0f;
    for (int i = threadIdx.x; i < NBLOCKS; i += NTHREADS)
        acc += g_partials[i];

    #pragma unroll
    for (int off = 16; off > 0; off >>= 1)
        acc += __shfl_xor_sync(0xFFFFFFFFu, acc, off);

    __shared__ float warp_sums[NTHREADS / 32];
    int lane = threadIdx.x & 31;
    int wid  = threadIdx.x >> 5;
    if (lane == 0) warp_sums[wid] = acc;
    __syncthreads();

    if (wid == 0) {
        float v = (lane < NTHREADS / 32) ? warp_sums[lane] : 0.0f;
        #pragma unroll
        for (int off = 4; off > 0; off >>= 1)
            v += __shfl_xor_sync(0xFFFFFFFFu, v, off);
        if (lane == 0) d_out[0] = v * inv_n;
    }
}

extern "C" void kernel_launch(void* const* d_in, const int* in_sizes, int n_in,
                              void* d_out, int out_size) {
    const float* output = (const float*)d_in[0];  // [N, 2] f32
    const int*   target = (const int*)d_in[1];    // [N] int32

    long long n  = (long long)in_sizes[1];  // N
    long long nq = n / 4;                   // groups of 4 rows

    floss_partial_kernel<<<NBLOCKS, NTHREADS>>>(output, target, nq);
    floss_final_kernel<<<1, NTHREADS>>>((float*)d_out, 1.0f / (float)n);
}

// round 4
// speedup vs baseline: 1.0508x; 1.0508x over previous
#include <cuda_runtime.h>

// FLoss: mean((1 - output[i, target[i]])^2)
// output: f32 [N,2]; target: int32 [N]. HBM-bound: 192 MB in, 4 B out.
// Single fused kernel: per-block partials + last-block final reduction.

#define NBLOCKS 2048
#define NTHREADS 256

__device__ float        g_partials[NBLOCKS];
__device__ unsigned int g_done_count = 0;  // atomicInc wraps to 0 -> replay-safe

__device__ __forceinline__ float quad_term(float4 v0, float4 v1, int4 t) {
    float a = (t.x == 0) ? v0.x : v0.y;
    float b = (t.y == 0) ? v0.z : v0.w;
    float c = (t.z == 0) ? v1.x : v1.y;
    float d = (t.w == 0) ? v1.z : v1.w;
    float da = 1.0f - a, db = 1.0f - b, dc = 1.0f - c, dd = 1.0f - d;
    return fmaf(da, da, db * db) + fmaf(dc, dc, dd * dd);
}

__device__ __forceinline__ float block_reduce(float acc, float* warp_sums) {
    #pragma unroll
    for (int off = 16; off > 0; off >>= 1)
        acc += __shfl_xor_sync(0xFFFFFFFFu, acc, off);
    int lane = threadIdx.x & 31;
    int wid  = threadIdx.x >> 5;
    if (lane == 0) warp_sums[wid] = acc;
    __syncthreads();
    float v = 0.0f;
    if (wid == 0) {
        v = (lane < NTHREADS / 32) ? warp_sums[lane] : 0.0f;
        #pragma unroll
        for (int off = 4; off > 0; off >>= 1)
            v += __shfl_xor_sync(0xFFFFFFFFu, v, off);
    }
    return v;  // valid in warp 0 lane 0
}

__global__ __launch_bounds__(NTHREADS)
void floss_fused_kernel(const float* __restrict__ out,
                        const int* __restrict__ tgt,
                        long long nq /* = N/4 */,
                        float inv_n,
                        float* __restrict__ d_out) {
    const float4* outv = reinterpret_cast<const float4*>(out);  // 2 rows per float4
    const int4*   tgtv = reinterpret_cast<const int4*>(tgt);    // 4 targets per int4

    float acc = 0.0f;
    long long j = (long long)blockIdx.x * NTHREADS + threadIdx.x;
    const long long stride = (long long)NBLOCKS * NTHREADS;

    // Unroll-by-2 grid-stride: 6 independent streaming loads in flight.
    for (; j + stride < nq; j += 2 * stride) {
        long long k = j + stride;
        float4 a0 = __ldcs(&outv[2 * j]);
        float4 a1 = __ldcs(&outv[2 * j + 1]);
        int4   ta = __ldcs(&tgtv[j]);
        float4 b0 = __ldcs(&outv[2 * k]);
        float4 b1 = __ldcs(&outv[2 * k + 1]);
        int4   tb = __ldcs(&tgtv[k]);
        acc += quad_term(a0, a1, ta);
        acc += quad_term(b0, b1, tb);
    }
    for (; j < nq; j += stride) {
        float4 a0 = __ldcs(&outv[2 * j]);
        float4 a1 = __ldcs(&outv[2 * j + 1]);
        int4   ta = __ldcs(&tgtv[j]);
        acc += quad_term(a0, a1, ta);
    }

    __shared__ float warp_sums[NTHREADS / 32];
    float bsum = block_reduce(acc, warp_sums);

    __shared__ bool is_last;
    if (threadIdx.x == 0) {
        g_partials[blockIdx.x] = bsum;
        __threadfence();
        // wraps back to 0 after NBLOCKS increments -> safe for graph replay
        unsigned int prev = atomicInc(&g_done_count, NBLOCKS - 1);
        is_last = (prev == NBLOCKS - 1);
    }
    __syncthreads();

    if (is_last) {
        float facc = 0.0f;
        for (int i = threadIdx.x; i < NBLOCKS; i += NTHREADS)
            facc += g_partials[i];
        __syncthreads();  // reuse warp_sums safely
        float total = block_reduce(facc, warp_sums);
        if (threadIdx.x == 0) d_out[0] = total * inv_n;
    }
}

extern "C" void kernel_launch(void* const* d_in, const int* in_sizes, int n_in,
                              void* d_out, int out_size) {
    const float* output = (const float*)d_in[0];  // [N, 2] f32
    const int*   target = (const int*)d_in[1];    // [N] int32

    long long n  = (long long)in_sizes[1];  // N
    long long nq = n / 4;                   // groups of 4 rows

    floss_fused_kernel<<<NBLOCKS, NTHREADS>>>(output, target, nq,
                                              1.0f / (float)n, (float*)d_out);
}

// round 5
// speedup vs baseline: 1.1281x; 1.0736x over previous
#include <cuda_runtime.h>

// FLoss: mean((1 - output[i, target[i]])^2)
// output: f32 [N,2]; target: int32 [N]. HBM-bound: 192 MB in, 4 B out.
// Single fused kernel: per-block partials + last-block final reduction.

#define NBLOCKS 1536
#define NTHREADS 256

__device__ float        g_partials[NBLOCKS];
__device__ unsigned int g_done_count = 0;  // atomicInc wraps to 0 -> replay-safe

__device__ __forceinline__ float quad_term(float4 v0, float4 v1, int4 t) {
    float a = (t.x == 0) ? v0.x : v0.y;
    float b = (t.y == 0) ? v0.z : v0.w;
    float c = (t.z == 0) ? v1.x : v1.y;
    float d = (t.w == 0) ? v1.z : v1.w;
    float da = 1.0f - a, db = 1.0f - b, dc = 1.0f - c, dd = 1.0f - d;
    return fmaf(da, da, db * db) + fmaf(dc, dc, dd * dd);
}

__device__ __forceinline__ float block_reduce(float acc, float* warp_sums) {
    #pragma unroll
    for (int off = 16; off > 0; off >>= 1)
        acc += __shfl_xor_sync(0xFFFFFFFFu, acc, off);
    int lane = threadIdx.x & 31;
    int wid  = threadIdx.x >> 5;
    if (lane == 0) warp_sums[wid] = acc;
    __syncthreads();
    float v = 0.0f;
    if (wid == 0) {
        v = (lane < NTHREADS / 32) ? warp_sums[lane] : 0.0f;
        #pragma unroll
        for (int off = 4; off > 0; off >>= 1)
            v += __shfl_xor_sync(0xFFFFFFFFu, v, off);
    }
    return v;  // valid in warp 0 lane 0
}

__global__ __launch_bounds__(NTHREADS)
void floss_fused_kernel(const float* __restrict__ out,
                        const int* __restrict__ tgt,
                        long long nq /* = N/4 */,
                        float inv_n,
                        float* __restrict__ d_out) {
    const float4* outv = reinterpret_cast<const float4*>(out);  // 2 rows per float4
    const int4*   tgtv = reinterpret_cast<const int4*>(tgt);    // 4 targets per int4

    float acc = 0.0f;
    long long j = (long long)blockIdx.x * NTHREADS + threadIdx.x;
    const long long stride = (long long)NBLOCKS * NTHREADS;

    // Unroll-by-4: 12 independent streaming loads in flight per thread.
    for (; j + 3 * stride < nq; j += 4 * stride) {
        long long j1 = j + stride, j2 = j + 2 * stride, j3 = j + 3 * stride;
        float4 a0 = __ldcs(&outv[2 * j]);
        float4 a1 = __ldcs(&outv[2 * j + 1]);
        float4 b0 = __ldcs(&outv[2 * j1]);
        float4 b1 = __ldcs(&outv[2 * j1 + 1]);
        float4 c0 = __ldcs(&outv[2 * j2]);
        float4 c1 = __ldcs(&outv[2 * j2 + 1]);
        float4 d0 = __ldcs(&outv[2 * j3]);
        float4 d1 = __ldcs(&outv[2 * j3 + 1]);
        int4   ta = __ldcs(&tgtv[j]);
        int4   tb = __ldcs(&tgtv[j1]);
        int4   tc = __ldcs(&tgtv[j2]);
        int4   td = __ldcs(&tgtv[j3]);
        acc += quad_term(a0, a1, ta);
        acc += quad_term(b0, b1, tb);
        acc += quad_term(c0, c1, tc);
        acc += quad_term(d0, d1, td);
    }
    // Remainder
    for (; j < nq; j += stride) {
        float4 a0 = __ldcs(&outv[2 * j]);
        float4 a1 = __ldcs(&outv[2 * j + 1]);
        int4   ta = __ldcs(&tgtv[j]);
        acc += quad_term(a0, a1, ta);
    }

    __shared__ float warp_sums[NTHREADS / 32];
    float bsum = block_reduce(acc, warp_sums);

    __shared__ bool is_last;
    if (threadIdx.x == 0) {
        g_partials[blockIdx.x] = bsum;
        __threadfence();
        unsigned int prev = atomicInc(&g_done_count, NBLOCKS - 1);
        is_last = (prev == NBLOCKS - 1);
    }
    __syncthreads();

    if (is_last) {
        float facc = 0.0f;
        for (int i = threadIdx.x; i < NBLOCKS; i += NTHREADS)
            facc += g_partials[i];
        __syncthreads();  // warp_sums reuse safe
        float total = block_reduce(facc, warp_sums);
        if (threadIdx.x == 0) d_out[0] = total * inv_n;
    }
}

extern "C" void kernel_launch(void* const* d_in, const int* in_sizes, int n_in,
                              void* d_out, int out_size) {
    const float* output = (const float*)d_in[0];  // [N, 2] f32
    const int*   target = (const int*)d_in[1];    // [N] int32

    long long n  = (long long)in_sizes[1];  // N
    long long nq = n / 4;                   // groups of 4 rows

    floss_fused_kernel<<<NBLOCKS, NTHREADS>>>(output, target, nq,
                                              1.0f / (float)n, (float*)d_out);
}